// round 13
// baseline (speedup 1.0000x reference)
#include <cuda_runtime.h>
#include <cub/cub.cuh>
#include <math.h>

#define NN 100000
#define DD 128
#define KE 64
#define EE 800000
#define SSZ 800000
#define HH 256
#define KINS 40000
#define UNDN 80000
#define TOTN 880000
#define OUTX 12800000
#define BANDW 3e-4f
#define BANDCAP 65536

typedef unsigned long long u64;
typedef unsigned int u32;

__device__ float g_P[(size_t)NN * HH];
__device__ float g_Q[(size_t)NN * HH];
__device__ float g_poss32[SSZ];
__device__ float g_possref[SSZ];
__device__ u64   g_k1a[UNDN], g_k1b[UNDN];
__device__ float g_v1a[UNDN], g_v1b[UNDN];
__device__ u64   g_k2a[TOTN], g_k2b[TOTN];
__device__ float g_v2a[TOTN], g_v2b[TOTN];
__device__ int   g_flag[TOTN], g_seg[TOTN];
__device__ u32   g_hist[256];
__device__ u32   g_state[8];   // 0:prefix 1:rem 5:R 6:T 7:tieCnt
__device__ u32   g_cut;
__device__ u32   g_T32;
__device__ u32   g_nband;
__device__ int   g_band[BANDCAP];
__device__ u32   g_ties[1 << 16];
__device__ int   g_sel[KINS + 1024];
__device__ unsigned char g_tmp[1u << 26];

// ---------------- f32x2 packed FMA helpers ----------------
__device__ __forceinline__ u64 pack2(float lo, float hi) {
    u64 r;
    asm("mov.b64 %0, {%1, %2};" : "=l"(r) : "r"(__float_as_uint(lo)), "r"(__float_as_uint(hi)));
    return r;
}
__device__ __forceinline__ void unpack2(u64 v, float& lo, float& hi) {
    u32 a, b;
    asm("mov.b64 {%0, %1}, %2;" : "=r"(a), "=r"(b) : "l"(v));
    lo = __uint_as_float(a); hi = __uint_as_float(b);
}
__device__ __forceinline__ u64 fma2(u64 a, u64 b, u64 c) {
    u64 d;
    asm("fma.rn.f32x2 %0, %1, %2, %3;" : "=l"(d) : "l"(a), "l"(b), "l"(c));
    return d;
}

// ---------------- Threefry-2x32-20, key (0,1234); partitionable: bits = o0^o1, ctr (0,j) ----
__device__ __forceinline__ void tf1234(u32 a, u32 b, u32& o0, u32& o1) {
    const u32 ks0 = 0u, ks1 = 1234u, ks2 = 0x1BD11BDAu ^ 1234u;
    u32 x0 = a + ks0, x1 = b + ks1;
#define R_(r) { x0 += x1; x1 = (x1 << (r)) | (x1 >> (32 - (r))); x1 ^= x0; }
    R_(13) R_(15) R_(26) R_(6)   x0 += ks1; x1 += ks2 + 1u;
    R_(17) R_(29) R_(16) R_(24)  x0 += ks2; x1 += ks0 + 2u;
    R_(13) R_(15) R_(26) R_(6)   x0 += ks0; x1 += ks1 + 3u;
    R_(17) R_(29) R_(16) R_(24)  x0 += ks1; x1 += ks2 + 4u;
    R_(13) R_(15) R_(26) R_(6)   x0 += ks2; x1 += ks0 + 5u;
#undef R_
    o0 = x0; o1 = x1;
}
__device__ __forceinline__ u32 bits_at(u32 j) {
    u32 o0, o1; tf1234(0u, j, o0, o1); return o0 ^ o1;
}
__device__ __forceinline__ float jax_unif(u32 b) {
    float f = __uint_as_float((b >> 9) | 0x3F800000u) - 1.0f;
    return fmaxf(1e-10f, f + 1e-10f);
}

// ---------------- init (split so edge_logit is kernel launch #6) ----------------
__global__ void zero_meta() {
    int i = threadIdx.x;
    if (i < 256) g_hist[i] = 0u;
    if (i < 8) g_state[i] = 0u;
    if (i == 0) { g_cut = 0u; g_nband = 0u; g_T32 = 0u; }
}
__global__ void zero_pad(float* __restrict__ out) {
    int i = blockIdx.x * blockDim.x + threadIdx.x;
    int st = gridDim.x * blockDim.x;
    for (int j = i; j < UNDN; j += st) { g_k2a[EE + j] = 0ull; g_v2a[EE + j] = 0.f; }
    for (int j = i; j < 3 * TOTN; j += st) out[OUTX + j] = 0.f;
}
__global__ void tiny_aux() {
    int i = threadIdx.x;
    if (i < 32) g_ties[i] = 0u;
}

// ---------------- fp32 GEMM (FFMA2): P = x@W1[64:192]+b1 ; Q = x@W1[192:320] ----------------
__global__ __launch_bounds__(256, 2) void gemm_pq(const float* __restrict__ x,
                                                  const float* __restrict__ W1,
                                                  const float* __restrict__ b1) {
    __shared__ float xs[16][136];
    __shared__ float ws[16][64];
    int by = blockIdx.y;
    int isP = by < 4;
    int n0 = (by & 3) * 64;
    int m0 = blockIdx.x * 128;
    const float* W = W1 + (size_t)(isP ? 64 : 192) * HH;
    float* O = isP ? g_P : g_Q;
    int t = threadIdx.x, tx = t & 15, ty = t >> 4;
    u64 acc2[8][2];
#pragma unroll
    for (int i = 0; i < 8; i++) { acc2[i][0] = 0ull; acc2[i][1] = 0ull; }

    for (int k0 = 0; k0 < DD; k0 += 16) {
#pragma unroll
        for (int r = 0; r < 8; r++) {
            int idx = t + r * 256, m = idx >> 4, kk = idx & 15;
            float v = 0.f;
            if (m0 + m < NN) v = x[(size_t)(m0 + m) * DD + k0 + kk];
            xs[kk][m] = v;
        }
#pragma unroll
        for (int r = 0; r < 4; r++) {
            int idx = t + r * 256, kk = idx >> 6, nn = idx & 63;
            ws[kk][nn] = W[(size_t)(k0 + kk) * HH + n0 + nn];
        }
        __syncthreads();
#pragma unroll
        for (int kk = 0; kk < 16; kk++) {
            ulonglong2 bb = *(const ulonglong2*)&ws[kk][tx * 4];
#pragma unroll
            for (int i = 0; i < 8; i++) {
                float av = xs[kk][ty * 8 + i];
                u64 a2 = pack2(av, av);
                acc2[i][0] = fma2(a2, bb.x, acc2[i][0]);
                acc2[i][1] = fma2(a2, bb.y, acc2[i][1]);
            }
        }
        __syncthreads();
    }
#pragma unroll
    for (int i = 0; i < 8; i++) {
        int m = m0 + ty * 8 + i;
        if (m < NN) {
            float v0, v1, v2, v3;
            unpack2(acc2[i][0], v0, v1);
            unpack2(acc2[i][1], v2, v3);
            int n = n0 + tx * 4;
            if (isP) { v0 += b1[n]; v1 += b1[n + 1]; v2 += b1[n + 2]; v3 += b1[n + 3]; }
            float* dst = O + (size_t)m * HH + n;
            dst[0] = v0; dst[1] = v1; dst[2] = v2; dst[3] = v3;
        }
    }
}

// ---------------- fp32 batched edge logits + poss32 (FFMA2) ----------------
// 32 edges per block, 256 threads: warp w -> edges w*4..w*4+3, lane l -> hidden l*8..l*8+7
__global__ __launch_bounds__(256) void edge_logit(const float* __restrict__ ev,
                                                  const int* __restrict__ se,
                                                  const float* __restrict__ W1,
                                                  const float* __restrict__ W2,
                                                  const float* __restrict__ b2) {
    __shared__ float s[32][64];
    __shared__ float wt[16][256];
    __shared__ float part0[32][33], part1[32][33];
    __shared__ float ws2[512];
    __shared__ int eu[32], evv[32];
    int t = threadIdx.x;
    int w = t >> 5, l = t & 31;
    int eBase = blockIdx.x * 32;

    if (t < 32) eu[t] = se[eBase + t];
    else if (t < 64) evv[t - 32] = se[SSZ + eBase + (t - 32)];
    ws2[t] = W2[t];
    ws2[t + 256] = W2[t + 256];
    __syncthreads();

    {
        int e = t >> 3, k0 = (t & 7) * 8;
        const float* pu = ev + (size_t)eu[e] * KE + k0;
        const float* pv = ev + (size_t)evv[e] * KE + k0;
        float4 a0 = *(const float4*)pu, a1 = *(const float4*)(pu + 4);
        float4 b0 = *(const float4*)pv, b1v = *(const float4*)(pv + 4);
        float d;
        d = a0.x - b0.x;  s[e][k0 + 0] = d * d;
        d = a0.y - b0.y;  s[e][k0 + 1] = d * d;
        d = a0.z - b0.z;  s[e][k0 + 2] = d * d;
        d = a0.w - b0.w;  s[e][k0 + 3] = d * d;
        d = a1.x - b1v.x; s[e][k0 + 4] = d * d;
        d = a1.y - b1v.y; s[e][k0 + 5] = d * d;
        d = a1.z - b1v.z; s[e][k0 + 6] = d * d;
        d = a1.w - b1v.w; s[e][k0 + 7] = d * d;
    }

    u64 acc2[4][4];
#pragma unroll
    for (int i = 0; i < 4; i++)
#pragma unroll
        for (int j = 0; j < 4; j++) acc2[i][j] = 0ull;

    int h0 = l * 8;
    for (int k0 = 0; k0 < KE; k0 += 16) {
        __syncthreads();
        {
            int f = t * 16;
            int kk = f >> 8, n = f & 255;
            const float* src = W1 + (size_t)(k0 + kk) * HH + n;
            float4* dst = (float4*)&wt[kk][n];
            dst[0] = ((const float4*)src)[0];
            dst[1] = ((const float4*)src)[1];
            dst[2] = ((const float4*)src)[2];
            dst[3] = ((const float4*)src)[3];
        }
        __syncthreads();
#pragma unroll
        for (int kk = 0; kk < 16; kk++) {
            ulonglong2 wA = *(const ulonglong2*)&wt[kk][h0];
            ulonglong2 wB = *(const ulonglong2*)&wt[kk][h0 + 4];
#pragma unroll
            for (int i = 0; i < 4; i++) {
                float sv = s[w * 4 + i][k0 + kk];
                u64 sv2 = pack2(sv, sv);
                acc2[i][0] = fma2(sv2, wA.x, acc2[i][0]);
                acc2[i][1] = fma2(sv2, wA.y, acc2[i][1]);
                acc2[i][2] = fma2(sv2, wB.x, acc2[i][2]);
                acc2[i][3] = fma2(sv2, wB.y, acc2[i][3]);
            }
        }
    }

#pragma unroll
    for (int i = 0; i < 4; i++) {
        int e = w * 4 + i;
        const float* Pr = g_P + (size_t)eu[e] * HH + h0;
        const float* Qr = g_Q + (size_t)evv[e] * HH + h0;
        float4 p0 = ((const float4*)Pr)[0], p1 = ((const float4*)Pr)[1];
        float4 q0 = ((const float4*)Qr)[0], q1 = ((const float4*)Qr)[1];
        float a[8];
        unpack2(acc2[i][0], a[0], a[1]);
        unpack2(acc2[i][1], a[2], a[3]);
        unpack2(acc2[i][2], a[4], a[5]);
        unpack2(acc2[i][3], a[6], a[7]);
        a[0] += p0.x + q0.x; a[1] += p0.y + q0.y;
        a[2] += p0.z + q0.z; a[3] += p0.w + q0.w;
        a[4] += p1.x + q1.x; a[5] += p1.y + q1.y;
        a[6] += p1.z + q1.z; a[7] += p1.w + q1.w;
        float pl0 = 0.f, pl1 = 0.f;
#pragma unroll
        for (int j = 0; j < 8; j++) {
            float r = fmaxf(a[j], 0.f);
            pl0 = fmaf(r, ws2[(h0 + j) * 2], pl0);
            pl1 = fmaf(r, ws2[(h0 + j) * 2 + 1], pl1);
        }
        part0[l][e] = pl0;
        part1[l][e] = pl1;
    }
    __syncthreads();

    if (t < 32) {
        int e = t;
        float l0 = 0.f, l1 = 0.f;
#pragma unroll 8
        for (int ll = 0; ll < 32; ll++) { l0 += part0[ll][e]; l1 += part1[ll][e]; }
        l0 += b2[0]; l1 += b2[1];
        int eg = eBase + e;
        float m = fmaxf(l0, l1);
        float e0 = expf(l0 - m), e1 = expf(l1 - m);
        float den = e0 + e1;
        float p0 = e0 / den, p1 = e1 / den;
        float lp0 = logf(p0 + 1e-8f), lp1 = logf(p1 + 1e-8f);
        float u0 = jax_unif(bits_at(2u * (u32)eg));
        float u1 = jax_unif(bits_at(2u * (u32)eg + 1u));
        float gg0 = -logf(-logf(u0));
        float gg1 = -logf(-logf(u1));
        float z0 = lp0 + gg0, z1 = lp1 + gg1;
        float m2 = fmaxf(z0, z1);
        float q0 = expf(z0 - m2), q1 = expf(z1 - m2);
        float poss = q0 / (q0 + q1);
        g_poss32[eg] = fminf(fmaxf(poss, 1e-6f), 1.0f);
    }
}

// ---------------- 8-bit radix select (shared-mem hist) ----------------
__global__ void hist_k(const float* __restrict__ p, int shift, int first) {
    __shared__ u32 h[256];
    int t = threadIdx.x;
    h[t] = 0u;
    __syncthreads();
    u32 prefix = first ? 0u : g_state[0];
    int i = blockIdx.x * 256 + t;
    for (; i < SSZ; i += gridDim.x * 256) {
        u32 b = __float_as_uint(p[i]);
        if (first || ((b >> (shift + 8)) == prefix))
            atomicAdd(&h[(b >> shift) & 255u], 1u);
    }
    __syncthreads();
    if (h[t]) atomicAdd(&g_hist[t], h[t]);
}
__global__ void scan_k(int first, int last) {
    u32 rem = first ? (u32)KINS : g_state[1];
    u32 prefix = first ? 0u : g_state[0];
    u32 acc = 0;
    for (int b = 255; b >= 0; b--) {
        u32 h = g_hist[b];
        if (acc + h >= rem) { prefix = (prefix << 8) | (u32)b; rem = rem - acc; break; }
        acc += h;
    }
    g_state[0] = prefix;
    g_state[1] = rem;
    if (last) { g_state[6] = prefix; g_state[5] = rem; g_state[7] = 0u; }
    for (int i = 0; i < 256; i++) g_hist[i] = 0u;
}
__global__ void save_T32_k() { g_T32 = g_state[6]; }

// ---------------- band: possref = poss32; collect |poss-T32|<=BANDW ----------------
__global__ void band_k() {
    float fT = __uint_as_float(g_T32);
    int i = blockIdx.x * blockDim.x + threadIdx.x;
    for (; i < SSZ; i += gridDim.x * blockDim.x) {
        float p = g_poss32[i];
        g_possref[i] = p;
        if (fabsf(p - fT) <= BANDW) {
            u32 pos = atomicAdd(&g_nband, 1u);
            if (pos < BANDCAP) g_band[pos] = i;
        }
    }
}

// ---------------- fp64 exact recompute for band edges (grid-stride, 4 accumulators) ----
__global__ __launch_bounds__(256) void band64_k(const float* __restrict__ x,
                                                const float* __restrict__ ev,
                                                const int* __restrict__ se,
                                                const float* __restrict__ W1,
                                                const float* __restrict__ b1,
                                                const float* __restrict__ W2,
                                                const float* __restrict__ b2) {
    u32 nb = g_nband; if (nb > BANDCAP) nb = BANDCAP;
    int t = threadIdx.x;
    __shared__ double sd[KE];
    __shared__ float xu[DD], xv[DD];
    __shared__ double r0[256], r1[256];
    for (u32 bid = blockIdx.x; bid < nb; bid += gridDim.x) {
        int e = g_band[bid];
        int u = se[e], v = se[SSZ + e];
        if (t < KE) {
            float d = ev[(size_t)u * KE + t] - ev[(size_t)v * KE + t];
            float d2 = d * d;
            sd[t] = (double)d2;
        }
        if (t < DD) xu[t] = x[(size_t)u * DD + t];
        else xv[t - DD] = x[(size_t)v * DD + (t - DD)];
        __syncthreads();
        int h = t;
        double a0 = (double)b1[h], a1 = 0.0, a2 = 0.0, a3 = 0.0;
#pragma unroll 4
        for (int k = 0; k < KE; k += 4) {
            a0 = fma(sd[k],     (double)W1[(size_t)k * HH + h], a0);
            a1 = fma(sd[k + 1], (double)W1[(size_t)(k + 1) * HH + h], a1);
            a2 = fma(sd[k + 2], (double)W1[(size_t)(k + 2) * HH + h], a2);
            a3 = fma(sd[k + 3], (double)W1[(size_t)(k + 3) * HH + h], a3);
        }
#pragma unroll 4
        for (int k = 0; k < DD; k += 4) {
            a0 = fma((double)xu[k],     (double)W1[(size_t)(64 + k) * HH + h], a0);
            a1 = fma((double)xu[k + 1], (double)W1[(size_t)(65 + k) * HH + h], a1);
            a2 = fma((double)xu[k + 2], (double)W1[(size_t)(66 + k) * HH + h], a2);
            a3 = fma((double)xu[k + 3], (double)W1[(size_t)(67 + k) * HH + h], a3);
        }
#pragma unroll 4
        for (int k = 0; k < DD; k += 4) {
            a0 = fma((double)xv[k],     (double)W1[(size_t)(192 + k) * HH + h], a0);
            a1 = fma((double)xv[k + 1], (double)W1[(size_t)(193 + k) * HH + h], a1);
            a2 = fma((double)xv[k + 2], (double)W1[(size_t)(194 + k) * HH + h], a2);
            a3 = fma((double)xv[k + 3], (double)W1[(size_t)(195 + k) * HH + h], a3);
        }
        double acc = ((a0 + a1) + (a2 + a3));
        acc = acc > 0.0 ? acc : 0.0;
        r0[h] = acc * (double)W2[2 * h];
        r1[h] = acc * (double)W2[2 * h + 1];
        __syncthreads();
        for (int o = 128; o > 0; o >>= 1) {
            if (t < o) { r0[t] += r0[t + o]; r1[t] += r1[t + o]; }
            __syncthreads();
        }
        if (t == 0) {
            float l0 = (float)r0[0], l1 = (float)r1[0];
            float m = fmaxf(l0, l1);
            float e0 = (float)exp((double)(l0 - m));
            float e1 = (float)exp((double)(l1 - m));
            float den = e0 + e1;
            float p0 = e0 / den, p1 = e1 / den;
            float lp0 = (float)log((double)(p0 + 1e-8f));
            float lp1 = (float)log((double)(p1 + 1e-8f));
            float u0 = jax_unif(bits_at(2u * (u32)e));
            float u1 = jax_unif(bits_at(2u * (u32)e + 1u));
            float li0 = (float)log((double)u0);
            float li1 = (float)log((double)u1);
            float gg0 = -(float)log((double)(-li0));
            float gg1 = -(float)log((double)(-li1));
            float z0 = lp0 + gg0, z1 = lp1 + gg1;
            float m2 = fmaxf(z0, z1);
            float q0 = (float)exp((double)(z0 - m2));
            float q1 = (float)exp((double)(z1 - m2));
            float poss = q0 / (q0 + q1);
            g_possref[e] = fminf(fmaxf(poss, 1e-6f), 1.0f);
        }
        __syncthreads();
    }
}

// ---------------- ties / flags / scatter ----------------
__global__ void tie_collect_k() {
    u32 T = g_state[6];
    int i = blockIdx.x * blockDim.x + threadIdx.x;
    for (; i < SSZ; i += gridDim.x * blockDim.x) {
        if (__float_as_uint(g_possref[i]) == T) {
            u32 p = atomicAdd(&g_state[7], 1u);
            if (p < (1u << 16)) g_ties[p] = (u32)i;
        }
    }
}
__global__ void tie_resolve_k() {
    u32 n = g_state[7]; if (n > (1u << 16)) n = 1u << 16;
    u32 R = g_state[5];
    if (R >= n) { g_cut = (u32)SSZ; return; }
    u32 lo = 0, hi = (u32)SSZ;
    while (lo < hi) {
        u32 mid = (lo + hi) >> 1;
        u32 c = 0;
        for (u32 t = 0; t < n; t++) if (g_ties[t] < mid) c++;
        if (c < R) lo = mid + 1; else hi = mid;
    }
    g_cut = lo;
}
__global__ void flag_sel_k() {
    u32 T = g_state[6], C = g_cut;
    int i = blockIdx.x * blockDim.x + threadIdx.x;
    for (; i < SSZ; i += gridDim.x * blockDim.x) {
        u32 b = __float_as_uint(g_possref[i]);
        g_flag[i] = (b > T) || (b == T && (u32)i < C);
    }
}
__global__ void scatter_sel_k() {
    int i = blockIdx.x * blockDim.x + threadIdx.x;
    for (; i < SSZ; i += gridDim.x * blockDim.x) {
        if (g_flag[i]) {
            int p = g_seg[i] - 1;
            if (p < KINS) g_sel[p] = i;
        }
    }
}

// ---------------- coalesce ----------------
__global__ void build_und_k(const int* __restrict__ se) {
    int i = blockIdx.x * blockDim.x + threadIdx.x;
    if (i >= KINS) return;
    int e = g_sel[i];
    u32 u = (u32)se[e], v = (u32)se[SSZ + e];
    float w = g_possref[e];
    g_k1a[i] = ((u64)u << 17) | v; g_v1a[i] = w;
    g_k1a[KINS + i] = ((u64)v << 17) | u; g_v1a[KINS + i] = w;
}
__global__ void flags1_k() {
    int i = blockIdx.x * blockDim.x + threadIdx.x;
    if (i >= UNDN) return;
    g_flag[i] = (i == 0) || (g_k1b[i] != g_k1b[i - 1]);
}
__global__ void coal1_k() {
    int i = blockIdx.x * blockDim.x + threadIdx.x;
    if (i >= UNDN || !g_flag[i]) return;
    float sm = 0.f, c = 0.f; int j = i;
    do { sm += g_v1b[j]; c += 1.f; j++; } while (j < UNDN && !g_flag[j]);
    int sg = g_seg[i] - 1;
    g_k2a[EE + sg] = g_k1b[i];
    g_v2a[EE + sg] = sm / fmaxf(c, 1.f);
}
__global__ void build_e2_k(const int* __restrict__ ei, const float* __restrict__ ew) {
    int i = blockIdx.x * blockDim.x + threadIdx.x;
    if (i >= EE) return;
    g_k2a[i] = ((u64)(u32)ei[i] << 17) | (u32)ei[EE + i];
    g_v2a[i] = ew[i];
}
__global__ void flags2_k() {
    int i = blockIdx.x * blockDim.x + threadIdx.x;
    if (i >= TOTN) return;
    g_flag[i] = (i == 0) || (g_k2b[i] != g_k2b[i - 1]);
}
__global__ void coal2_k(float* __restrict__ out) {
    int i = blockIdx.x * blockDim.x + threadIdx.x;
    if (i >= TOTN || !g_flag[i]) return;
    float sm = 0.f; int j = i;
    do { sm += g_v2b[j]; j++; } while (j < TOTN && !g_flag[j]);
    int sg = g_seg[i] - 1;
    u64 k = g_k2b[i];
    out[OUTX + sg] = (float)(u32)(k >> 17);
    out[OUTX + TOTN + sg] = (float)(u32)(k & 0x1FFFFu);
    out[OUTX + 2 * TOTN + sg] = sm;
}

extern "C" void kernel_launch(void* const* d_in, const int* in_sizes, int n_in,
                              void* d_out, int out_size) {
    const float* x  = (const float*)d_in[0];
    const float* ev = (const float*)d_in[1];
    const float* ew = (const float*)d_in[2];
    const float* W1 = (const float*)d_in[3];
    const float* b1 = (const float*)d_in[4];
    const float* W2 = (const float*)d_in[5];
    const float* b2 = (const float*)d_in[6];
    const int*   ei = (const int*)d_in[7];
    const int*   se = (const int*)d_in[8];
    float* out = (float*)d_out;

    void *tmp, *k1a, *k1b, *v1a, *v1b, *k2a, *k2b, *v2a, *v2b, *flg, *seg;
    void *p32, *pref;
    cudaGetSymbolAddress(&tmp, g_tmp);
    cudaGetSymbolAddress(&k1a, g_k1a); cudaGetSymbolAddress(&k1b, g_k1b);
    cudaGetSymbolAddress(&v1a, g_v1a); cudaGetSymbolAddress(&v1b, g_v1b);
    cudaGetSymbolAddress(&k2a, g_k2a); cudaGetSymbolAddress(&k2b, g_k2b);
    cudaGetSymbolAddress(&v2a, g_v2a); cudaGetSymbolAddress(&v2b, g_v2b);
    cudaGetSymbolAddress(&flg, g_flag); cudaGetSymbolAddress(&seg, g_seg);
    cudaGetSymbolAddress(&p32, g_poss32); cudaGetSymbolAddress(&pref, g_possref);
    size_t tb;

    // launches 1-5 (reordered so edge_logit is #6 for ncu -s 5 -c 1)
    zero_meta<<<1, 256>>>();
    zero_pad<<<2048, 256>>>(out);
    build_e2_k<<<(EE + 255) / 256, 256>>>(ei, ew);
    gemm_pq<<<dim3((NN + 127) / 128, 8), 256>>>(x, W1, b1);
    tiny_aux<<<1, 32>>>();
    // launch 6: the suspected-dominant kernel
    edge_logit<<<SSZ / 32, 256>>>(ev, se, W1, W2, b2);

    // round 1: approximate threshold on poss32
    hist_k<<<296, 256>>>((const float*)p32, 24, 1); scan_k<<<1, 1>>>(1, 0);
    hist_k<<<296, 256>>>((const float*)p32, 16, 0); scan_k<<<1, 1>>>(0, 0);
    hist_k<<<296, 256>>>((const float*)p32, 8, 0);  scan_k<<<1, 1>>>(0, 0);
    hist_k<<<296, 256>>>((const float*)p32, 0, 0);  scan_k<<<1, 1>>>(0, 1);
    save_T32_k<<<1, 1>>>();

    // band refinement
    band_k<<<296, 256>>>();
    band64_k<<<2048, 256>>>(x, ev, se, W1, b1, W2, b2);

    // round 2: exact select on refined values
    hist_k<<<296, 256>>>((const float*)pref, 24, 1); scan_k<<<1, 1>>>(1, 0);
    hist_k<<<296, 256>>>((const float*)pref, 16, 0); scan_k<<<1, 1>>>(0, 0);
    hist_k<<<296, 256>>>((const float*)pref, 8, 0);  scan_k<<<1, 1>>>(0, 0);
    hist_k<<<296, 256>>>((const float*)pref, 0, 0);  scan_k<<<1, 1>>>(0, 1);
    tie_collect_k<<<296, 256>>>();
    tie_resolve_k<<<1, 1>>>();
    flag_sel_k<<<296, 256>>>();

    tb = sizeof(g_tmp);
    cub::DeviceScan::InclusiveSum(tmp, tb, (int*)flg, (int*)seg, SSZ);
    scatter_sel_k<<<296, 256>>>();

    build_und_k<<<(KINS + 255) / 256, 256>>>(se);
    tb = sizeof(g_tmp);
    cub::DeviceRadixSort::SortPairs(tmp, tb, (u64*)k1a, (u64*)k1b,
                                    (float*)v1a, (float*)v1b, UNDN, 0, 34);
    flags1_k<<<(UNDN + 255) / 256, 256>>>();
    tb = sizeof(g_tmp);
    cub::DeviceScan::InclusiveSum(tmp, tb, (int*)flg, (int*)seg, UNDN);
    coal1_k<<<(UNDN + 255) / 256, 256>>>();

    tb = sizeof(g_tmp);
    cub::DeviceRadixSort::SortPairs(tmp, tb, (u64*)k2a, (u64*)k2b,
                                    (float*)v2a, (float*)v2b, TOTN, 0, 34);
    flags2_k<<<(TOTN + 255) / 256, 256>>>();
    tb = sizeof(g_tmp);
    cub::DeviceScan::InclusiveSum(tmp, tb, (int*)flg, (int*)seg, TOTN);
    coal2_k<<<(TOTN + 255) / 256, 256>>>(out);

    cudaMemcpyAsync(out, x, (size_t)OUTX * sizeof(float),
                    cudaMemcpyDeviceToDevice, 0);
}

// round 14
// speedup vs baseline: 1.0014x; 1.0014x over previous
#include <cuda_runtime.h>
#include <cub/cub.cuh>
#include <math.h>

#define NN 100000
#define DD 128
#define KE 64
#define EE 800000
#define SSZ 800000
#define HH 256
#define KINS 40000
#define UNDN 80000
#define TOTN 880000
#define OUTX 12800000
#define BANDW 3e-4f
#define BANDCAP 65536

typedef unsigned long long u64;
typedef unsigned int u32;

__device__ float g_P[(size_t)NN * HH];
__device__ float g_Q[(size_t)NN * HH];
__device__ float g_poss32[SSZ];
__device__ float g_possref[SSZ];
__device__ u64   g_k1a[UNDN], g_k1b[UNDN];
__device__ float g_v1a[UNDN], g_v1b[UNDN];
__device__ u64   g_k2a[TOTN], g_k2b[TOTN];
__device__ float g_v2a[TOTN], g_v2b[TOTN];
__device__ int   g_flag[TOTN], g_seg[TOTN];
__device__ u32   g_hist[256];
__device__ u32   g_state[8];   // 0:prefix 1:rem 5:R 6:T 7:tieCnt
__device__ u32   g_cut;
__device__ u32   g_T32;
__device__ u32   g_nband;
__device__ int   g_band[BANDCAP];
__device__ u32   g_ties[1 << 16];
__device__ int   g_sel[KINS + 1024];
__device__ unsigned char g_tmp[1u << 26];

// ---------------- f32x2 packed FMA helpers ----------------
__device__ __forceinline__ u64 pack2(float lo, float hi) {
    u64 r;
    asm("mov.b64 %0, {%1, %2};" : "=l"(r) : "r"(__float_as_uint(lo)), "r"(__float_as_uint(hi)));
    return r;
}
__device__ __forceinline__ void unpack2(u64 v, float& lo, float& hi) {
    u32 a, b;
    asm("mov.b64 {%0, %1}, %2;" : "=r"(a), "=r"(b) : "l"(v));
    lo = __uint_as_float(a); hi = __uint_as_float(b);
}
__device__ __forceinline__ u64 fma2(u64 a, u64 b, u64 c) {
    u64 d;
    asm("fma.rn.f32x2 %0, %1, %2, %3;" : "=l"(d) : "l"(a), "l"(b), "l"(c));
    return d;
}

// ---------------- Threefry-2x32-20, key (0,1234); partitionable: bits = o0^o1, ctr (0,j) ----
__device__ __forceinline__ void tf1234(u32 a, u32 b, u32& o0, u32& o1) {
    const u32 ks0 = 0u, ks1 = 1234u, ks2 = 0x1BD11BDAu ^ 1234u;
    u32 x0 = a + ks0, x1 = b + ks1;
#define R_(r) { x0 += x1; x1 = (x1 << (r)) | (x1 >> (32 - (r))); x1 ^= x0; }
    R_(13) R_(15) R_(26) R_(6)   x0 += ks1; x1 += ks2 + 1u;
    R_(17) R_(29) R_(16) R_(24)  x0 += ks2; x1 += ks0 + 2u;
    R_(13) R_(15) R_(26) R_(6)   x0 += ks0; x1 += ks1 + 3u;
    R_(17) R_(29) R_(16) R_(24)  x0 += ks1; x1 += ks2 + 4u;
    R_(13) R_(15) R_(26) R_(6)   x0 += ks2; x1 += ks0 + 5u;
#undef R_
    o0 = x0; o1 = x1;
}
__device__ __forceinline__ u32 bits_at(u32 j) {
    u32 o0, o1; tf1234(0u, j, o0, o1); return o0 ^ o1;
}
__device__ __forceinline__ float jax_unif(u32 b) {
    float f = __uint_as_float((b >> 9) | 0x3F800000u) - 1.0f;
    return fmaxf(1e-10f, f + 1e-10f);
}

// ---------------- init (split so edge_logit is kernel launch #6) ----------------
__global__ void zero_meta() {
    int i = threadIdx.x;
    if (i < 256) g_hist[i] = 0u;
    if (i < 8) g_state[i] = 0u;
    if (i == 0) { g_cut = 0u; g_nband = 0u; g_T32 = 0u; }
}
__global__ void zero_pad(float* __restrict__ out) {
    int i = blockIdx.x * blockDim.x + threadIdx.x;
    int st = gridDim.x * blockDim.x;
    for (int j = i; j < UNDN; j += st) { g_k2a[EE + j] = 0ull; g_v2a[EE + j] = 0.f; }
    for (int j = i; j < 3 * TOTN; j += st) out[OUTX + j] = 0.f;
}
__global__ void tiny_aux() {
    int i = threadIdx.x;
    if (i < 32) g_ties[i] = 0u;
}

// ---------------- fp32 GEMM (FFMA2): P = x@W1[64:192]+b1 ; Q = x@W1[192:320] ----------------
__global__ __launch_bounds__(256, 2) void gemm_pq(const float* __restrict__ x,
                                                  const float* __restrict__ W1,
                                                  const float* __restrict__ b1) {
    __shared__ float xs[16][136];
    __shared__ float ws[16][64];
    int by = blockIdx.y;
    int isP = by < 4;
    int n0 = (by & 3) * 64;
    int m0 = blockIdx.x * 128;
    const float* W = W1 + (size_t)(isP ? 64 : 192) * HH;
    float* O = isP ? g_P : g_Q;
    int t = threadIdx.x, tx = t & 15, ty = t >> 4;
    u64 acc2[8][2];
#pragma unroll
    for (int i = 0; i < 8; i++) { acc2[i][0] = 0ull; acc2[i][1] = 0ull; }

    for (int k0 = 0; k0 < DD; k0 += 16) {
#pragma unroll
        for (int r = 0; r < 8; r++) {
            int idx = t + r * 256, m = idx >> 4, kk = idx & 15;
            float v = 0.f;
            if (m0 + m < NN) v = x[(size_t)(m0 + m) * DD + k0 + kk];
            xs[kk][m] = v;
        }
#pragma unroll
        for (int r = 0; r < 4; r++) {
            int idx = t + r * 256, kk = idx >> 6, nn = idx & 63;
            ws[kk][nn] = W[(size_t)(k0 + kk) * HH + n0 + nn];
        }
        __syncthreads();
#pragma unroll
        for (int kk = 0; kk < 16; kk++) {
            ulonglong2 bb = *(const ulonglong2*)&ws[kk][tx * 4];
#pragma unroll
            for (int i = 0; i < 8; i++) {
                float av = xs[kk][ty * 8 + i];
                u64 a2 = pack2(av, av);
                acc2[i][0] = fma2(a2, bb.x, acc2[i][0]);
                acc2[i][1] = fma2(a2, bb.y, acc2[i][1]);
            }
        }
        __syncthreads();
    }
#pragma unroll
    for (int i = 0; i < 8; i++) {
        int m = m0 + ty * 8 + i;
        if (m < NN) {
            float v0, v1, v2, v3;
            unpack2(acc2[i][0], v0, v1);
            unpack2(acc2[i][1], v2, v3);
            int n = n0 + tx * 4;
            if (isP) { v0 += b1[n]; v1 += b1[n + 1]; v2 += b1[n + 2]; v3 += b1[n + 3]; }
            float* dst = O + (size_t)m * HH + n;
            dst[0] = v0; dst[1] = v1; dst[2] = v2; dst[3] = v3;
        }
    }
}

// ---------------- fp32 batched edge logits + poss32 (FFMA2) ----------------
// 32 edges per block, 256 threads: warp w -> edges w*4..w*4+3, lane l -> hidden l*8..l*8+7
__global__ __launch_bounds__(256) void edge_logit(const float* __restrict__ ev,
                                                  const int* __restrict__ se,
                                                  const float* __restrict__ W1,
                                                  const float* __restrict__ W2,
                                                  const float* __restrict__ b2) {
    __shared__ float s[32][64];
    __shared__ float wt[16][256];
    __shared__ float part0[32][33], part1[32][33];
    __shared__ float ws2[512];
    __shared__ int eu[32], evv[32];
    int t = threadIdx.x;
    int w = t >> 5, l = t & 31;
    int eBase = blockIdx.x * 32;

    if (t < 32) eu[t] = se[eBase + t];
    else if (t < 64) evv[t - 32] = se[SSZ + eBase + (t - 32)];
    ws2[t] = W2[t];
    ws2[t + 256] = W2[t + 256];
    __syncthreads();

    {
        int e = t >> 3, k0 = (t & 7) * 8;
        const float* pu = ev + (size_t)eu[e] * KE + k0;
        const float* pv = ev + (size_t)evv[e] * KE + k0;
        float4 a0 = *(const float4*)pu, a1 = *(const float4*)(pu + 4);
        float4 b0 = *(const float4*)pv, b1v = *(const float4*)(pv + 4);
        float d;
        d = a0.x - b0.x;  s[e][k0 + 0] = d * d;
        d = a0.y - b0.y;  s[e][k0 + 1] = d * d;
        d = a0.z - b0.z;  s[e][k0 + 2] = d * d;
        d = a0.w - b0.w;  s[e][k0 + 3] = d * d;
        d = a1.x - b1v.x; s[e][k0 + 4] = d * d;
        d = a1.y - b1v.y; s[e][k0 + 5] = d * d;
        d = a1.z - b1v.z; s[e][k0 + 6] = d * d;
        d = a1.w - b1v.w; s[e][k0 + 7] = d * d;
    }

    u64 acc2[4][4];
#pragma unroll
    for (int i = 0; i < 4; i++)
#pragma unroll
        for (int j = 0; j < 4; j++) acc2[i][j] = 0ull;

    int h0 = l * 8;
    for (int k0 = 0; k0 < KE; k0 += 16) {
        __syncthreads();
        {
            int f = t * 16;
            int kk = f >> 8, n = f & 255;
            const float* src = W1 + (size_t)(k0 + kk) * HH + n;
            float4* dst = (float4*)&wt[kk][n];
            dst[0] = ((const float4*)src)[0];
            dst[1] = ((const float4*)src)[1];
            dst[2] = ((const float4*)src)[2];
            dst[3] = ((const float4*)src)[3];
        }
        __syncthreads();
#pragma unroll
        for (int kk = 0; kk < 16; kk++) {
            ulonglong2 wA = *(const ulonglong2*)&wt[kk][h0];
            ulonglong2 wB = *(const ulonglong2*)&wt[kk][h0 + 4];
#pragma unroll
            for (int i = 0; i < 4; i++) {
                float sv = s[w * 4 + i][k0 + kk];
                u64 sv2 = pack2(sv, sv);
                acc2[i][0] = fma2(sv2, wA.x, acc2[i][0]);
                acc2[i][1] = fma2(sv2, wA.y, acc2[i][1]);
                acc2[i][2] = fma2(sv2, wB.x, acc2[i][2]);
                acc2[i][3] = fma2(sv2, wB.y, acc2[i][3]);
            }
        }
    }

#pragma unroll
    for (int i = 0; i < 4; i++) {
        int e = w * 4 + i;
        const float* Pr = g_P + (size_t)eu[e] * HH + h0;
        const float* Qr = g_Q + (size_t)evv[e] * HH + h0;
        float4 p0 = ((const float4*)Pr)[0], p1 = ((const float4*)Pr)[1];
        float4 q0 = ((const float4*)Qr)[0], q1 = ((const float4*)Qr)[1];
        float a[8];
        unpack2(acc2[i][0], a[0], a[1]);
        unpack2(acc2[i][1], a[2], a[3]);
        unpack2(acc2[i][2], a[4], a[5]);
        unpack2(acc2[i][3], a[6], a[7]);
        a[0] += p0.x + q0.x; a[1] += p0.y + q0.y;
        a[2] += p0.z + q0.z; a[3] += p0.w + q0.w;
        a[4] += p1.x + q1.x; a[5] += p1.y + q1.y;
        a[6] += p1.z + q1.z; a[7] += p1.w + q1.w;
        float pl0 = 0.f, pl1 = 0.f;
#pragma unroll
        for (int j = 0; j < 8; j++) {
            float r = fmaxf(a[j], 0.f);
            pl0 = fmaf(r, ws2[(h0 + j) * 2], pl0);
            pl1 = fmaf(r, ws2[(h0 + j) * 2 + 1], pl1);
        }
        part0[l][e] = pl0;
        part1[l][e] = pl1;
    }
    __syncthreads();

    if (t < 32) {
        int e = t;
        float l0 = 0.f, l1 = 0.f;
#pragma unroll 8
        for (int ll = 0; ll < 32; ll++) { l0 += part0[ll][e]; l1 += part1[ll][e]; }
        l0 += b2[0]; l1 += b2[1];
        int eg = eBase + e;
        float m = fmaxf(l0, l1);
        float e0 = expf(l0 - m), e1 = expf(l1 - m);
        float den = e0 + e1;
        float p0 = e0 / den, p1 = e1 / den;
        float lp0 = logf(p0 + 1e-8f), lp1 = logf(p1 + 1e-8f);
        float u0 = jax_unif(bits_at(2u * (u32)eg));
        float u1 = jax_unif(bits_at(2u * (u32)eg + 1u));
        float gg0 = -logf(-logf(u0));
        float gg1 = -logf(-logf(u1));
        float z0 = lp0 + gg0, z1 = lp1 + gg1;
        float m2 = fmaxf(z0, z1);
        float q0 = expf(z0 - m2), q1 = expf(z1 - m2);
        float poss = q0 / (q0 + q1);
        g_poss32[eg] = fminf(fmaxf(poss, 1e-6f), 1.0f);
    }
}

// ---------------- 8-bit radix select (shared-mem hist) ----------------
__global__ void hist_k(const float* __restrict__ p, int shift, int first) {
    __shared__ u32 h[256];
    int t = threadIdx.x;
    h[t] = 0u;
    __syncthreads();
    u32 prefix = first ? 0u : g_state[0];
    int i = blockIdx.x * 256 + t;
    for (; i < SSZ; i += gridDim.x * 256) {
        u32 b = __float_as_uint(p[i]);
        if (first || ((b >> (shift + 8)) == prefix))
            atomicAdd(&h[(b >> shift) & 255u], 1u);
    }
    __syncthreads();
    if (h[t]) atomicAdd(&g_hist[t], h[t]);
}
__global__ void scan_k(int first, int last) {
    u32 rem = first ? (u32)KINS : g_state[1];
    u32 prefix = first ? 0u : g_state[0];
    u32 acc = 0;
    for (int b = 255; b >= 0; b--) {
        u32 h = g_hist[b];
        if (acc + h >= rem) { prefix = (prefix << 8) | (u32)b; rem = rem - acc; break; }
        acc += h;
    }
    g_state[0] = prefix;
    g_state[1] = rem;
    if (last) { g_state[6] = prefix; g_state[5] = rem; g_state[7] = 0u; }
    for (int i = 0; i < 256; i++) g_hist[i] = 0u;
}
__global__ void save_T32_k() { g_T32 = g_state[6]; }

// ---------------- band: possref = poss32; collect |poss-T32|<=BANDW ----------------
__global__ void band_k() {
    float fT = __uint_as_float(g_T32);
    int i = blockIdx.x * blockDim.x + threadIdx.x;
    for (; i < SSZ; i += gridDim.x * blockDim.x) {
        float p = g_poss32[i];
        g_possref[i] = p;
        if (fabsf(p - fT) <= BANDW) {
            u32 pos = atomicAdd(&g_nband, 1u);
            if (pos < BANDCAP) g_band[pos] = i;
        }
    }
}

// ---------------- fp64 exact recompute for band edges (grid-stride, 4 accumulators) ----
__global__ __launch_bounds__(256) void band64_k(const float* __restrict__ x,
                                                const float* __restrict__ ev,
                                                const int* __restrict__ se,
                                                const float* __restrict__ W1,
                                                const float* __restrict__ b1,
                                                const float* __restrict__ W2,
                                                const float* __restrict__ b2) {
    u32 nb = g_nband; if (nb > BANDCAP) nb = BANDCAP;
    int t = threadIdx.x;
    __shared__ double sd[KE];
    __shared__ float xu[DD], xv[DD];
    __shared__ double r0[256], r1[256];
    for (u32 bid = blockIdx.x; bid < nb; bid += gridDim.x) {
        int e = g_band[bid];
        int u = se[e], v = se[SSZ + e];
        if (t < KE) {
            float d = ev[(size_t)u * KE + t] - ev[(size_t)v * KE + t];
            float d2 = d * d;
            sd[t] = (double)d2;
        }
        if (t < DD) xu[t] = x[(size_t)u * DD + t];
        else xv[t - DD] = x[(size_t)v * DD + (t - DD)];
        __syncthreads();
        int h = t;
        double a0 = (double)b1[h], a1 = 0.0, a2 = 0.0, a3 = 0.0;
#pragma unroll 4
        for (int k = 0; k < KE; k += 4) {
            a0 = fma(sd[k],     (double)W1[(size_t)k * HH + h], a0);
            a1 = fma(sd[k + 1], (double)W1[(size_t)(k + 1) * HH + h], a1);
            a2 = fma(sd[k + 2], (double)W1[(size_t)(k + 2) * HH + h], a2);
            a3 = fma(sd[k + 3], (double)W1[(size_t)(k + 3) * HH + h], a3);
        }
#pragma unroll 4
        for (int k = 0; k < DD; k += 4) {
            a0 = fma((double)xu[k],     (double)W1[(size_t)(64 + k) * HH + h], a0);
            a1 = fma((double)xu[k + 1], (double)W1[(size_t)(65 + k) * HH + h], a1);
            a2 = fma((double)xu[k + 2], (double)W1[(size_t)(66 + k) * HH + h], a2);
            a3 = fma((double)xu[k + 3], (double)W1[(size_t)(67 + k) * HH + h], a3);
        }
#pragma unroll 4
        for (int k = 0; k < DD; k += 4) {
            a0 = fma((double)xv[k],     (double)W1[(size_t)(192 + k) * HH + h], a0);
            a1 = fma((double)xv[k + 1], (double)W1[(size_t)(193 + k) * HH + h], a1);
            a2 = fma((double)xv[k + 2], (double)W1[(size_t)(194 + k) * HH + h], a2);
            a3 = fma((double)xv[k + 3], (double)W1[(size_t)(195 + k) * HH + h], a3);
        }
        double acc = ((a0 + a1) + (a2 + a3));
        acc = acc > 0.0 ? acc : 0.0;
        r0[h] = acc * (double)W2[2 * h];
        r1[h] = acc * (double)W2[2 * h + 1];
        __syncthreads();
        for (int o = 128; o > 0; o >>= 1) {
            if (t < o) { r0[t] += r0[t + o]; r1[t] += r1[t + o]; }
            __syncthreads();
        }
        if (t == 0) {
            float l0 = (float)r0[0], l1 = (float)r1[0];
            float m = fmaxf(l0, l1);
            float e0 = (float)exp((double)(l0 - m));
            float e1 = (float)exp((double)(l1 - m));
            float den = e0 + e1;
            float p0 = e0 / den, p1 = e1 / den;
            float lp0 = (float)log((double)(p0 + 1e-8f));
            float lp1 = (float)log((double)(p1 + 1e-8f));
            float u0 = jax_unif(bits_at(2u * (u32)e));
            float u1 = jax_unif(bits_at(2u * (u32)e + 1u));
            float li0 = (float)log((double)u0);
            float li1 = (float)log((double)u1);
            float gg0 = -(float)log((double)(-li0));
            float gg1 = -(float)log((double)(-li1));
            float z0 = lp0 + gg0, z1 = lp1 + gg1;
            float m2 = fmaxf(z0, z1);
            float q0 = (float)exp((double)(z0 - m2));
            float q1 = (float)exp((double)(z1 - m2));
            float poss = q0 / (q0 + q1);
            g_possref[e] = fminf(fmaxf(poss, 1e-6f), 1.0f);
        }
        __syncthreads();
    }
}

// ---------------- ties / flags / scatter ----------------
__global__ void tie_collect_k() {
    u32 T = g_state[6];
    int i = blockIdx.x * blockDim.x + threadIdx.x;
    for (; i < SSZ; i += gridDim.x * blockDim.x) {
        if (__float_as_uint(g_possref[i]) == T) {
            u32 p = atomicAdd(&g_state[7], 1u);
            if (p < (1u << 16)) g_ties[p] = (u32)i;
        }
    }
}
__global__ void tie_resolve_k() {
    u32 n = g_state[7]; if (n > (1u << 16)) n = 1u << 16;
    u32 R = g_state[5];
    if (R >= n) { g_cut = (u32)SSZ; return; }
    u32 lo = 0, hi = (u32)SSZ;
    while (lo < hi) {
        u32 mid = (lo + hi) >> 1;
        u32 c = 0;
        for (u32 t = 0; t < n; t++) if (g_ties[t] < mid) c++;
        if (c < R) lo = mid + 1; else hi = mid;
    }
    g_cut = lo;
}
__global__ void flag_sel_k() {
    u32 T = g_state[6], C = g_cut;
    int i = blockIdx.x * blockDim.x + threadIdx.x;
    for (; i < SSZ; i += gridDim.x * blockDim.x) {
        u32 b = __float_as_uint(g_possref[i]);
        g_flag[i] = (b > T) || (b == T && (u32)i < C);
    }
}
__global__ void scatter_sel_k() {
    int i = blockIdx.x * blockDim.x + threadIdx.x;
    for (; i < SSZ; i += gridDim.x * blockDim.x) {
        if (g_flag[i]) {
            int p = g_seg[i] - 1;
            if (p < KINS) g_sel[p] = i;
        }
    }
}

// ---------------- coalesce ----------------
__global__ void build_und_k(const int* __restrict__ se) {
    int i = blockIdx.x * blockDim.x + threadIdx.x;
    if (i >= KINS) return;
    int e = g_sel[i];
    u32 u = (u32)se[e], v = (u32)se[SSZ + e];
    float w = g_possref[e];
    g_k1a[i] = ((u64)u << 17) | v; g_v1a[i] = w;
    g_k1a[KINS + i] = ((u64)v << 17) | u; g_v1a[KINS + i] = w;
}
__global__ void flags1_k() {
    int i = blockIdx.x * blockDim.x + threadIdx.x;
    if (i >= UNDN) return;
    g_flag[i] = (i == 0) || (g_k1b[i] != g_k1b[i - 1]);
}
__global__ void coal1_k() {
    int i = blockIdx.x * blockDim.x + threadIdx.x;
    if (i >= UNDN || !g_flag[i]) return;
    float sm = 0.f, c = 0.f; int j = i;
    do { sm += g_v1b[j]; c += 1.f; j++; } while (j < UNDN && !g_flag[j]);
    int sg = g_seg[i] - 1;
    g_k2a[EE + sg] = g_k1b[i];
    g_v2a[EE + sg] = sm / fmaxf(c, 1.f);
}
__global__ void build_e2_k(const int* __restrict__ ei, const float* __restrict__ ew) {
    int i = blockIdx.x * blockDim.x + threadIdx.x;
    if (i >= EE) return;
    g_k2a[i] = ((u64)(u32)ei[i] << 17) | (u32)ei[EE + i];
    g_v2a[i] = ew[i];
}
__global__ void flags2_k() {
    int i = blockIdx.x * blockDim.x + threadIdx.x;
    if (i >= TOTN) return;
    g_flag[i] = (i == 0) || (g_k2b[i] != g_k2b[i - 1]);
}
__global__ void coal2_k(float* __restrict__ out) {
    int i = blockIdx.x * blockDim.x + threadIdx.x;
    if (i >= TOTN || !g_flag[i]) return;
    float sm = 0.f; int j = i;
    do { sm += g_v2b[j]; j++; } while (j < TOTN && !g_flag[j]);
    int sg = g_seg[i] - 1;
    u64 k = g_k2b[i];
    out[OUTX + sg] = (float)(u32)(k >> 17);
    out[OUTX + TOTN + sg] = (float)(u32)(k & 0x1FFFFu);
    out[OUTX + 2 * TOTN + sg] = sm;
}

extern "C" void kernel_launch(void* const* d_in, const int* in_sizes, int n_in,
                              void* d_out, int out_size) {
    const float* x  = (const float*)d_in[0];
    const float* ev = (const float*)d_in[1];
    const float* ew = (const float*)d_in[2];
    const float* W1 = (const float*)d_in[3];
    const float* b1 = (const float*)d_in[4];
    const float* W2 = (const float*)d_in[5];
    const float* b2 = (const float*)d_in[6];
    const int*   ei = (const int*)d_in[7];
    const int*   se = (const int*)d_in[8];
    float* out = (float*)d_out;

    void *tmp, *k1a, *k1b, *v1a, *v1b, *k2a, *k2b, *v2a, *v2b, *flg, *seg;
    void *p32, *pref;
    cudaGetSymbolAddress(&tmp, g_tmp);
    cudaGetSymbolAddress(&k1a, g_k1a); cudaGetSymbolAddress(&k1b, g_k1b);
    cudaGetSymbolAddress(&v1a, g_v1a); cudaGetSymbolAddress(&v1b, g_v1b);
    cudaGetSymbolAddress(&k2a, g_k2a); cudaGetSymbolAddress(&k2b, g_k2b);
    cudaGetSymbolAddress(&v2a, g_v2a); cudaGetSymbolAddress(&v2b, g_v2b);
    cudaGetSymbolAddress(&flg, g_flag); cudaGetSymbolAddress(&seg, g_seg);
    cudaGetSymbolAddress(&p32, g_poss32); cudaGetSymbolAddress(&pref, g_possref);
    size_t tb;

    // launches 1-5 (reordered so edge_logit is #6 for ncu -s 5 -c 1)
    zero_meta<<<1, 256>>>();
    zero_pad<<<2048, 256>>>(out);
    build_e2_k<<<(EE + 255) / 256, 256>>>(ei, ew);
    gemm_pq<<<dim3((NN + 127) / 128, 8), 256>>>(x, W1, b1);
    tiny_aux<<<1, 32>>>();
    // launch 6: the suspected-dominant kernel
    edge_logit<<<SSZ / 32, 256>>>(ev, se, W1, W2, b2);

    // round 1: approximate threshold on poss32
    hist_k<<<296, 256>>>((const float*)p32, 24, 1); scan_k<<<1, 1>>>(1, 0);
    hist_k<<<296, 256>>>((const float*)p32, 16, 0); scan_k<<<1, 1>>>(0, 0);
    hist_k<<<296, 256>>>((const float*)p32, 8, 0);  scan_k<<<1, 1>>>(0, 0);
    hist_k<<<296, 256>>>((const float*)p32, 0, 0);  scan_k<<<1, 1>>>(0, 1);
    save_T32_k<<<1, 1>>>();

    // band refinement
    band_k<<<296, 256>>>();
    band64_k<<<2048, 256>>>(x, ev, se, W1, b1, W2, b2);

    // round 2: exact select on refined values
    hist_k<<<296, 256>>>((const float*)pref, 24, 1); scan_k<<<1, 1>>>(1, 0);
    hist_k<<<296, 256>>>((const float*)pref, 16, 0); scan_k<<<1, 1>>>(0, 0);
    hist_k<<<296, 256>>>((const float*)pref, 8, 0);  scan_k<<<1, 1>>>(0, 0);
    hist_k<<<296, 256>>>((const float*)pref, 0, 0);  scan_k<<<1, 1>>>(0, 1);
    tie_collect_k<<<296, 256>>>();
    tie_resolve_k<<<1, 1>>>();
    flag_sel_k<<<296, 256>>>();

    tb = sizeof(g_tmp);
    cub::DeviceScan::InclusiveSum(tmp, tb, (int*)flg, (int*)seg, SSZ);
    scatter_sel_k<<<296, 256>>>();

    build_und_k<<<(KINS + 255) / 256, 256>>>(se);
    tb = sizeof(g_tmp);
    cub::DeviceRadixSort::SortPairs(tmp, tb, (u64*)k1a, (u64*)k1b,
                                    (float*)v1a, (float*)v1b, UNDN, 0, 34);
    flags1_k<<<(UNDN + 255) / 256, 256>>>();
    tb = sizeof(g_tmp);
    cub::DeviceScan::InclusiveSum(tmp, tb, (int*)flg, (int*)seg, UNDN);
    coal1_k<<<(UNDN + 255) / 256, 256>>>();

    tb = sizeof(g_tmp);
    cub::DeviceRadixSort::SortPairs(tmp, tb, (u64*)k2a, (u64*)k2b,
                                    (float*)v2a, (float*)v2b, TOTN, 0, 34);
    flags2_k<<<(TOTN + 255) / 256, 256>>>();
    tb = sizeof(g_tmp);
    cub::DeviceScan::InclusiveSum(tmp, tb, (int*)flg, (int*)seg, TOTN);
    coal2_k<<<(TOTN + 255) / 256, 256>>>(out);

    cudaMemcpyAsync(out, x, (size_t)OUTX * sizeof(float),
                    cudaMemcpyDeviceToDevice, 0);
}